// round 15
// baseline (speedup 1.0000x reference)
#include <cuda_runtime.h>
#include <cuda_fp16.h>
#include <math.h>

#define HIDDEN 64
#define MBATCH 32
#define ATOM   64
#define NUM_RBF 300

#define S_INT   512
#define TAB_ROWS 513                    // row s = h(s*H_STEP), s in [0,512]
#define H_STEP  (10.0f / 512.0f)
#define INV_H   51.2f

typedef unsigned long long u64;

// device scratch (no allocations allowed)
__device__ __align__(16) unsigned g_table_h[515 * 32];   // fp16x2 table, row=128B
__device__ unsigned g_bar;                               // monotonic grid barrier

__device__ __forceinline__ float softplus_f(float v) {
    return fmaxf(v, 0.0f) + log1pf(expf(-fabsf(v)));
}

// packed f32x2 helpers (Blackwell FFMA2 / FADD2)
__device__ __forceinline__ u64 fma2(u64 a, u64 b, u64 c) {
    u64 d; asm("fma.rn.f32x2 %0, %1, %2, %3;" : "=l"(d) : "l"(a), "l"(b), "l"(c)); return d;
}
__device__ __forceinline__ u64 add2(u64 a, u64 b) {
    u64 d; asm("add.rn.f32x2 %0, %1, %2;" : "=l"(d) : "l"(a), "l"(b)); return d;
}
__device__ __forceinline__ u64 pack2(float a, float b) {
    u64 d; asm("mov.b64 %0, {%1, %2};" : "=l"(d) : "f"(a), "f"(b)); return d;
}
__device__ __forceinline__ float2 unpk2(u64 v) {
    float2 f; asm("mov.b64 {%0, %1}, %2;" : "=f"(f.x), "=f"(f.y) : "l"(v)); return f;
}
__device__ __forceinline__ u64 dup2(float v) {
    u64 d; asm("mov.b64 %0, {%1, %1};" : "=l"(d) : "f"(v)); return d;
}
__device__ __forceinline__ unsigned h2bits(float w) {
    __half2 h = __float2half2_rn(w);
    return *reinterpret_cast<unsigned*>(&h);
}
__device__ __forceinline__ __half2 bits2h(unsigned u) {
    return *reinterpret_cast<__half2*>(&u);
}

// ---------------------------------------------------------------------------
// FUSED kernel: 128 blocks = (m, j-group of 16), 1024 threads.
//   Phase A: each CTA builds its 4 table samples (CTA 127: 5), computes v1
//            for its m into smem, stages W2^T/W3^T + biases, computes W4.
//   Grid barrier (all 128 CTAs co-resident: <=2 CTAs/SM needed on 148 SMs).
//   Phase B: R14 main loop (fp16 taps via __ldg, half-warp channel quads,
//            2 pairs/warp-iter) + fused epilogue.
// ---------------------------------------------------------------------------
// smem floats: V1s 4096 | W2Ts 4096 | W3Ts 4096 | B2s 64 | B3s 64 |
//              W4s 4096 | PARTs 4096 | PAIRs 1024 | V2s 1024 = 22656 = 90624 B
// Prep scratch overlays [W4s .. PAIRs end) = 9216 floats (A1: 7309, A2: 8704).
#define MAIN_SMEM (22656 * 4)
#define WPAD 41

__global__ void __launch_bounds__(1024) fused_kernel(
    const float* __restrict__ x, const float* __restrict__ dist,
    const float* __restrict__ W1, const float* __restrict__ b1,
    const float* __restrict__ W2, const float* __restrict__ b2,
    const float* __restrict__ W3, const float* __restrict__ b3,
    const float* __restrict__ Wd1, const float* __restrict__ bd1,
    const float* __restrict__ Wd2, const float* __restrict__ bd2,
    float* __restrict__ out)
{
    extern __shared__ float sh[];
    float* V1s  = sh;                     // 4096
    float* W2Ts = V1s + 4096;             // 4096
    float* W3Ts = W2Ts + 4096;            // 4096
    float* B2s  = W3Ts + 4096;            // 64
    float* B3s  = B2s + 64;               // 64
    float* W4s  = B3s + 64;               // 4096 (scratch early)
    float* PARTs= W4s + 4096;             // 4096 (scratch early)
    float* PAIRs= PARTs + 4096;           // 1024 (scratch early)
    float* V2s  = PAIRs + 1024;           // 1024
    float* scr  = W4s;                    // contiguous 9216-float scratch

    const int tid = threadIdx.x;
    const int bid = blockIdx.x;
    const int m  = bid >> 2;
    const int j0 = (bid & 3) << 4;

    // ------------------- Phase A1: table samples -------------------
    {
        float* Wd1_s = scr;                  // 64 x 41
        float* Wd2_s = scr + 2624;           // 64 x 65
        float* rbf_s = scr + 6784;           // 5 x 41
        float* g_s   = scr + 6989;           // 5 x 64

        const int s0 = bid << 2;
        const int NS = (bid == 127) ? 5 : 4;
        const float dlo = (float)s0 * H_STEP;
        const float dhi = (float)(s0 + NS - 1) * H_STEP;
        int R0 = (int)ceilf((dlo - 1.5f) * 10.0f); if (R0 < 0) R0 = 0;
        int R1 = (int)floorf((dhi + 1.5f) * 10.0f); if (R1 > NUM_RBF - 1) R1 = NUM_RBF - 1;
        const int RW = R1 - R0 + 1;          // <= 36

        // windowed Wd1 slice (coalesced-ish reads, padded rows)
        #pragma unroll 3
        for (int idx = tid; idx < 64 * WPAD; idx += 1024) {
            int row = idx / WPAD;
            int col = idx - row * WPAD;
            Wd1_s[idx] = (col < RW) ? __ldg(&Wd1[row * NUM_RBF + R0 + col]) : 0.0f;
        }
        // Wd2 full, padded 65
        {
            float4 v = ((const float4*)Wd2)[tid];
            int e = tid << 2;
            float* dstp = Wd2_s + (e >> 6) * 65 + (e & 63);
            dstp[0] = v.x; dstp[1] = v.y; dstp[2] = v.z; dstp[3] = v.w;
        }
        // windowed RBF values
        if (tid < 5 * WPAD) {
            int q = tid / WPAD, rr = tid - q * WPAD;
            if (rr < RW && q < NS) {
                float dd = (float)(s0 + q) * H_STEP;
                float u = dd - 0.1f * (float)(R0 + rr);
                rbf_s[tid] = __expf(-10.0f * u * u);
            }
        }
        __syncthreads();

        const int q = tid >> 6;
        const int c = tid & 63;
        if (q < NS) {
            const int s = s0 + q;
            const float d = (float)s * H_STEP;
            int rlo = (int)ceilf((d - 1.5f) * 10.0f); if (rlo < R0) rlo = R0;
            int rhi = (int)floorf((d + 1.5f) * 10.0f); if (rhi > R1) rhi = R1;
            float p = bd1[c];
            const float* wrow = Wd1_s + c * WPAD - R0;
            const float* rrow = rbf_s + q * WPAD - R0;
            #pragma unroll 4
            for (int r = rlo; r <= rhi; r++) p = fmaf(wrow[r], rrow[r], p);
            g_s[q * 64 + c] = softplus_f(p);
        }
        __syncthreads();
        if (q < NS) {
            const int s = s0 + q;
            float qv = bd2[c];
            const float* w2row = Wd2_s + c * 65;
            const float* gg = g_s + q * 64;
            #pragma unroll 8
            for (int k = 0; k < 64; k++) qv = fmaf(w2row[k], gg[k], qv);
            ((__half*)g_table_h)[s * 64 + c] = __float2half_rn(softplus_f(qv));
        }
        __syncthreads();
    }

    // ------------------- Phase A2: v1 = x[m] @ W1^T + b1 -> V1s -------------------
    {
        float* W1p = scr;                // 64 x 68
        float* xp  = scr + 4352;         // 64 x 68
        {
            float4 vv = ((const float4*)W1)[tid];
            int e = tid << 2;
            *(float4*)(W1p + (e >> 6) * 68 + (e & 63)) = vv;
            float4 xv = ((const float4*)(x + m * 4096))[tid];
            *(float4*)(xp + (e >> 6) * 68 + (e & 63)) = xv;
        }
        __syncthreads();

        const int ii = tid & 63;         // source atom row
        const int oh = tid >> 6;         // output quad 0..15
        float4 acc = make_float4(0.f, 0.f, 0.f, 0.f);
        const float* xr = xp + ii * 68;
        const float* wr = W1p + oh * 4 * 68;
        #pragma unroll
        for (int c4 = 0; c4 < 16; c4++) {
            float4 xv = *(const float4*)(xr + c4 * 4);
            float4 w0 = *(const float4*)(wr + 0 * 68 + c4 * 4);
            float4 w1 = *(const float4*)(wr + 1 * 68 + c4 * 4);
            float4 w2 = *(const float4*)(wr + 2 * 68 + c4 * 4);
            float4 w3 = *(const float4*)(wr + 3 * 68 + c4 * 4);
            acc.x = fmaf(xv.x, w0.x, fmaf(xv.y, w0.y, fmaf(xv.z, w0.z, fmaf(xv.w, w0.w, acc.x))));
            acc.y = fmaf(xv.x, w1.x, fmaf(xv.y, w1.y, fmaf(xv.z, w1.z, fmaf(xv.w, w1.w, acc.y))));
            acc.z = fmaf(xv.x, w2.x, fmaf(xv.y, w2.y, fmaf(xv.z, w2.z, fmaf(xv.w, w2.w, acc.z))));
            acc.w = fmaf(xv.x, w3.x, fmaf(xv.y, w3.y, fmaf(xv.z, w3.z, fmaf(xv.w, w3.w, acc.w))));
        }
        float4 bv = *(const float4*)(b1 + oh * 4);
        acc.x += bv.x; acc.y += bv.y; acc.z += bv.z; acc.w += bv.w;
        *(float4*)(V1s + ii * 64 + oh * 4) = acc;
        __syncthreads();
    }

    // ------------------- Phase A3+A4: epilogue weights, biases, W4 -------------------
    {
        // W2^T / W3^T: transposed global reads, coalesced smem writes
        #pragma unroll 4
        for (int k = 0; k < 4; k++) {
            int idx = tid + (k << 10);
            int src = (idx & 63) * 64 + (idx >> 6);
            W2Ts[idx] = __ldg(&W2[src]);
            W3Ts[idx] = __ldg(&W3[src]);
        }
        if (tid < 64) B2s[tid] = b2[tid];
        else if (tid < 128) B3s[tid - 64] = b3[tid - 64];

        // per-pair quadratic weights around nearest node k (nodes k-1,k,k+1)
        const int i = tid >> 4, jj = tid & 15;
        float d = dist[(m * 64 + i) * 64 + j0 + jj];
        float t = d * INV_H;
        int k = __float2int_rn(t);
        k = min(max(k, 1), S_INT - 1);
        float u = t - (float)k;
        float wm = 0.5f * u * (u - 1.0f);
        float w0 = 1.0f - u * u;
        float wp = 0.5f * u * (u + 1.0f);
        float4 wk;
        wk.x = __uint_as_float(h2bits(wm));
        wk.y = __uint_as_float(h2bits(w0));
        wk.z = __uint_as_float(h2bits(wp));
        wk.w = __int_as_float((k - 1) << 7);   // byte offset of first tap row
        ((float4*)W4s)[tid] = wk;
    }

    // ------------------- Grid barrier (table visibility) -------------------
    __threadfence();
    __syncthreads();
    if (tid == 0) {
        unsigned old = atomicAdd(&g_bar, 1u);
        unsigned target = (old & ~127u) + 128u;
        while (*((volatile unsigned*)&g_bar) < target) { __nanosleep(64); }
        __threadfence();
    }
    __syncthreads();

    // ------------------- Phase B: main loop -------------------
    const int warp  = tid >> 5;
    const int jj    = warp & 15;     // destination atom
    const int ihalf = warp >> 4;     // 0..1 : i-range half
    const int t     = tid & 31;
    const int half  = t >> 4;        // even/odd i within the half-warp
    const int q     = t & 15;        // channel quad: channels 4q..4q+3

    u64 acc0 = 0ull, acc1 = 0ull;
    const char* tbg = (const char*)g_table_h + (q << 3);    // GLOBAL, L1-cached
    const char* v1b = (const char*)V1s + (q << 4);
    const float4* W4v = ((const float4*)W4s) + jj;
    const int i0 = (ihalf << 5) + half;                     // start i, step 2

    float4 wk = W4v[i0 << 4];                               // prefetch iter 0
    #pragma unroll 4
    for (int ii = 0; ii < 16; ii++) {
        const int i = i0 + (ii << 1);
        int koff = __float_as_int(wk.w);
        uint2 r0 = __ldg((const uint2*)(tbg + koff));
        uint2 r1 = __ldg((const uint2*)(tbg + koff + 128));
        uint2 r2 = __ldg((const uint2*)(tbg + koff + 256));
        ulonglong2 vv = *(const ulonglong2*)(v1b + (i << 8));
        float4 wk_n = (ii < 15) ? W4v[(i + 2) << 4] : wk;   // prefetch next
        __half2 wm2 = bits2h(__float_as_uint(wk.x));
        __half2 w02 = bits2h(__float_as_uint(wk.y));
        __half2 wp2 = bits2h(__float_as_uint(wk.z));
        __half2 hA = __hfma2(wm2, bits2h(r0.x),
                     __hfma2(w02, bits2h(r1.x), __hmul2(wp2, bits2h(r2.x))));
        __half2 hB = __hfma2(wm2, bits2h(r0.y),
                     __hfma2(w02, bits2h(r1.y), __hmul2(wp2, bits2h(r2.y))));
        float2 fA = __half22float2(hA);
        float2 fB = __half22float2(hB);
        acc0 = fma2(vv.x, pack2(fA.x, fA.y), acc0);
        acc1 = fma2(vv.y, pack2(fB.x, fB.y), acc1);
        wk = wk_n;
    }
    {
        const int slice = (ihalf << 1) | half;              // 0..3
        ulonglong2 r; r.x = acc0; r.y = acc1;
        ((ulonglong2*)PARTs)[slice * 256 + (jj << 4) + q] = r;
    }
    __syncthreads();

    // reduce 4 slices
    if (tid < 256) {
        const ulonglong2* pp = (const ulonglong2*)PARTs;
        ulonglong2 a0 = pp[tid];
        ulonglong2 a1 = pp[256 + tid];
        ulonglong2 a2 = pp[512 + tid];
        ulonglong2 a3 = pp[768 + tid];
        ulonglong2 r;
        r.x = add2(add2(a0.x, a1.x), add2(a2.x, a3.x));
        r.y = add2(add2(a0.y, a1.y), add2(a2.y, a3.y));
        ((ulonglong2*)PAIRs)[tid] = r;
    }
    __syncthreads();

    // epilogue: 8 warps, each handles 2 j-rows; lane = output pair (2t,2t+1)
    if (tid < 256) {
        const int g  = tid >> 5;      // 0..7
        const int tt = tid & 31;
        const int jj0 = g, jj1 = g + 8;

        u64 a0, a1;
        {
            u64 bp = ((const u64*)B2s)[tt];
            a0 = bp; a1 = bp;
            const float4* pr0 = (const float4*)(PAIRs + jj0 * 64);
            const float4* pr1 = (const float4*)(PAIRs + jj1 * 64);
            const u64* wv = (const u64*)W2Ts;
            #pragma unroll 4
            for (int c4 = 0; c4 < 16; c4++) {
                float4 p0 = pr0[c4];
                float4 p1 = pr1[c4];
                u64 w0 = wv[(c4 * 4 + 0) * 32 + tt];
                u64 w1 = wv[(c4 * 4 + 1) * 32 + tt];
                u64 w2 = wv[(c4 * 4 + 2) * 32 + tt];
                u64 w3 = wv[(c4 * 4 + 3) * 32 + tt];
                a0 = fma2(dup2(p0.x), w0, a0); a1 = fma2(dup2(p1.x), w0, a1);
                a0 = fma2(dup2(p0.y), w1, a0); a1 = fma2(dup2(p1.y), w1, a1);
                a0 = fma2(dup2(p0.z), w2, a0); a1 = fma2(dup2(p1.z), w2, a1);
                a0 = fma2(dup2(p0.w), w3, a0); a1 = fma2(dup2(p1.w), w3, a1);
            }
            float2 f0 = unpk2(a0), f1 = unpk2(a1);
            ((u64*)V2s)[jj0 * 32 + tt] = pack2(softplus_f(f0.x), softplus_f(f0.y));
            ((u64*)V2s)[jj1 * 32 + tt] = pack2(softplus_f(f1.x), softplus_f(f1.y));
        }
        __syncwarp();

        {
            u64 bp = ((const u64*)B3s)[tt];
            a0 = bp; a1 = bp;
            const float4* pr0 = (const float4*)(V2s + jj0 * 64);
            const float4* pr1 = (const float4*)(V2s + jj1 * 64);
            const u64* wv = (const u64*)W3Ts;
            #pragma unroll 4
            for (int c4 = 0; c4 < 16; c4++) {
                float4 p0 = pr0[c4];
                float4 p1 = pr1[c4];
                u64 w0 = wv[(c4 * 4 + 0) * 32 + tt];
                u64 w1 = wv[(c4 * 4 + 1) * 32 + tt];
                u64 w2 = wv[(c4 * 4 + 2) * 32 + tt];
                u64 w3 = wv[(c4 * 4 + 3) * 32 + tt];
                a0 = fma2(dup2(p0.x), w0, a0); a1 = fma2(dup2(p1.x), w0, a1);
                a0 = fma2(dup2(p0.y), w1, a0); a1 = fma2(dup2(p1.y), w1, a1);
                a0 = fma2(dup2(p0.z), w2, a0); a1 = fma2(dup2(p1.z), w2, a1);
                a0 = fma2(dup2(p0.w), w3, a0); a1 = fma2(dup2(p1.w), w3, a1);
            }
            const u64* xv = (const u64*)x;
            u64* ov = (u64*)out;
            int g0 = (m * 64 + j0 + jj0) * 32 + tt;
            int g1 = (m * 64 + j0 + jj1) * 32 + tt;
            float2 f0 = unpk2(a0), x0 = unpk2(xv[g0]);
            float2 f1 = unpk2(a1), x1 = unpk2(xv[g1]);
            ov[g0] = pack2(f0.x + x0.x, f0.y + x0.y);
            ov[g1] = pack2(f1.x + x1.x, f1.y + x1.y);
        }
    }
}

extern "C" void kernel_launch(void* const* d_in, const int* in_sizes, int n_in,
                              void* d_out, int out_size) {
    const float* x   = (const float*)d_in[0];
    const float* dist= (const float*)d_in[1];
    const float* W1  = (const float*)d_in[2];
    const float* b1  = (const float*)d_in[3];
    const float* W2  = (const float*)d_in[4];
    const float* b2  = (const float*)d_in[5];
    const float* W3  = (const float*)d_in[6];
    const float* b3  = (const float*)d_in[7];
    const float* Wd1 = (const float*)d_in[8];
    const float* bd1 = (const float*)d_in[9];
    const float* Wd2 = (const float*)d_in[10];
    const float* bd2 = (const float*)d_in[11];
    float* out = (float*)d_out;
    (void)in_sizes; (void)n_in; (void)out_size;

    cudaFuncSetAttribute(fused_kernel, cudaFuncAttributeMaxDynamicSharedMemorySize, MAIN_SMEM);
    fused_kernel<<<128, 1024, MAIN_SMEM>>>(x, dist, W1, b1, W2, b2, W3, b3,
                                           Wd1, bd1, Wd2, bd2, out);
}

// round 16
// speedup vs baseline: 1.1991x; 1.1991x over previous
#include <cuda_runtime.h>
#include <cuda_fp16.h>
#include <math.h>

#define HIDDEN 64
#define MBATCH 32
#define ATOM   64
#define NUM_RBF 300

#define S_INT   512
#define TAB_ROWS 513                    // row s = h(s*H_STEP), s in [0,512]
#define H_STEP  (10.0f / 512.0f)
#define INV_H   51.2f

typedef unsigned long long u64;

// device scratch (no allocations allowed)
__device__ __align__(16) unsigned g_table_h[515 * 32];   // fp16x2 table, row=128B
__device__ unsigned g_bar;                               // monotonic grid barrier

__device__ __forceinline__ float softplus_f(float v) {
    return fmaxf(v, 0.0f) + log1pf(expf(-fabsf(v)));
}

// packed f32x2 helpers (Blackwell FFMA2 / FADD2)
__device__ __forceinline__ u64 fma2(u64 a, u64 b, u64 c) {
    u64 d; asm("fma.rn.f32x2 %0, %1, %2, %3;" : "=l"(d) : "l"(a), "l"(b), "l"(c)); return d;
}
__device__ __forceinline__ u64 add2(u64 a, u64 b) {
    u64 d; asm("add.rn.f32x2 %0, %1, %2;" : "=l"(d) : "l"(a), "l"(b)); return d;
}
__device__ __forceinline__ u64 pack2(float a, float b) {
    u64 d; asm("mov.b64 %0, {%1, %2};" : "=l"(d) : "f"(a), "f"(b)); return d;
}
__device__ __forceinline__ float2 unpk2(u64 v) {
    float2 f; asm("mov.b64 {%0, %1}, %2;" : "=f"(f.x), "=f"(f.y) : "l"(v)); return f;
}
__device__ __forceinline__ u64 dup2(float v) {
    u64 d; asm("mov.b64 %0, {%1, %1};" : "=l"(d) : "f"(v)); return d;
}
__device__ __forceinline__ unsigned h2bits(float w) {
    __half2 h = __float2half2_rn(w);
    return *reinterpret_cast<unsigned*>(&h);
}
__device__ __forceinline__ __half2 bits2h(unsigned u) {
    return *reinterpret_cast<__half2*>(&u);
}

// ---------------------------------------------------------------------------
// FUSED kernel: 128 blocks = (m, j-group of 16), 1024 threads.
//   Phase A: 4 table samples per CTA (CTA 127: 5), v1 into smem,
//            W2^T/W3^T via tiled padded transpose, W4, biases.
//   Grid barrier (128 CTAs co-resident on 148 SMs).
//   Phase B: depth-2 software-pipelined main loop + fused epilogue.
// ---------------------------------------------------------------------------
// smem floats: V1s 4096 | W2Ts 4096 | W3Ts 4096 | B2s 64 | B3s 64 |
//              W4s 4096 | PARTs 4096 | PAIRs 1024 | V2s 1024 = 22656 = 90624 B
// Scratch overlays: A1/A2 use [W4s..] (9216 avail); transpose tile uses
// [PARTs..] (64x65 = 4160 <= 5120).
#define MAIN_SMEM (22656 * 4)
#define WPAD 41

__global__ void __launch_bounds__(1024) fused_kernel(
    const float* __restrict__ x, const float* __restrict__ dist,
    const float* __restrict__ W1, const float* __restrict__ b1,
    const float* __restrict__ W2, const float* __restrict__ b2,
    const float* __restrict__ W3, const float* __restrict__ b3,
    const float* __restrict__ Wd1, const float* __restrict__ bd1,
    const float* __restrict__ Wd2, const float* __restrict__ bd2,
    float* __restrict__ out)
{
    extern __shared__ float sh[];
    float* V1s  = sh;                     // 4096
    float* W2Ts = V1s + 4096;             // 4096
    float* W3Ts = W2Ts + 4096;            // 4096
    float* B2s  = W3Ts + 4096;            // 64
    float* B3s  = B2s + 64;               // 64
    float* W4s  = B3s + 64;               // 4096
    float* PARTs= W4s + 4096;             // 4096
    float* PAIRs= PARTs + 4096;           // 1024
    float* V2s  = PAIRs + 1024;           // 1024
    float* scr  = W4s;                    // A1/A2 scratch (9216 floats)
    float* Ttile= PARTs;                  // transpose tile 64x65 (4160 floats)

    const int tid = threadIdx.x;
    const int bid = blockIdx.x;
    const int m  = bid >> 2;
    const int j0 = (bid & 3) << 4;

    // ------------------- Phase A1: table samples -------------------
    {
        float* Wd1_s = scr;                  // 64 x 41
        float* Wd2_s = scr + 2624;           // 64 x 65
        float* rbf_s = scr + 6784;           // 5 x 41
        float* g_s   = scr + 6989;           // 5 x 64

        const int s0 = bid << 2;
        const int NS = (bid == 127) ? 5 : 4;
        const float dlo = (float)s0 * H_STEP;
        const float dhi = (float)(s0 + NS - 1) * H_STEP;
        int R0 = (int)ceilf((dlo - 1.5f) * 10.0f); if (R0 < 0) R0 = 0;
        int R1 = (int)floorf((dhi + 1.5f) * 10.0f); if (R1 > NUM_RBF - 1) R1 = NUM_RBF - 1;
        const int RW = R1 - R0 + 1;          // <= 33

        #pragma unroll 3
        for (int idx = tid; idx < 64 * WPAD; idx += 1024) {
            int row = idx / WPAD;
            int col = idx - row * WPAD;
            Wd1_s[idx] = (col < RW) ? __ldg(&Wd1[row * NUM_RBF + R0 + col]) : 0.0f;
        }
        {
            float4 v = ((const float4*)Wd2)[tid];
            int e = tid << 2;
            float* dstp = Wd2_s + (e >> 6) * 65 + (e & 63);
            dstp[0] = v.x; dstp[1] = v.y; dstp[2] = v.z; dstp[3] = v.w;
        }
        if (tid < 5 * WPAD) {
            int q = tid / WPAD, rr = tid - q * WPAD;
            if (rr < RW && q < NS) {
                float dd = (float)(s0 + q) * H_STEP;
                float u = dd - 0.1f * (float)(R0 + rr);
                rbf_s[tid] = __expf(-10.0f * u * u);
            }
        }
        __syncthreads();

        const int q = tid >> 6;
        const int c = tid & 63;
        if (q < NS) {
            const int s = s0 + q;
            const float d = (float)s * H_STEP;
            int rlo = (int)ceilf((d - 1.5f) * 10.0f); if (rlo < R0) rlo = R0;
            int rhi = (int)floorf((d + 1.5f) * 10.0f); if (rhi > R1) rhi = R1;
            float p = bd1[c];
            const float* wrow = Wd1_s + c * WPAD - R0;
            const float* rrow = rbf_s + q * WPAD - R0;
            #pragma unroll 4
            for (int r = rlo; r <= rhi; r++) p = fmaf(wrow[r], rrow[r], p);
            g_s[q * 64 + c] = softplus_f(p);
        }
        __syncthreads();
        if (q < NS) {
            const int s = s0 + q;
            float qv = bd2[c];
            const float* w2row = Wd2_s + c * 65;
            const float* gg = g_s + q * 64;
            #pragma unroll 8
            for (int k = 0; k < 64; k++) qv = fmaf(w2row[k], gg[k], qv);
            ((__half*)g_table_h)[s * 64 + c] = __float2half_rn(softplus_f(qv));
        }
        __syncthreads();
    }

    // ------------------- Phase A2: v1 = x[m] @ W1^T + b1 -> V1s -------------------
    {
        float* W1p = scr;                // 64 x 68
        float* xp  = scr + 4352;         // 64 x 68
        {
            float4 vv = ((const float4*)W1)[tid];
            int e = tid << 2;
            *(float4*)(W1p + (e >> 6) * 68 + (e & 63)) = vv;
            float4 xv = ((const float4*)(x + m * 4096))[tid];
            *(float4*)(xp + (e >> 6) * 68 + (e & 63)) = xv;
        }
        __syncthreads();

        const int ii = tid & 63;         // source atom row
        const int oh = tid >> 6;         // output quad 0..15
        float4 acc = make_float4(0.f, 0.f, 0.f, 0.f);
        const float* xr = xp + ii * 68;
        const float* wr = W1p + oh * 4 * 68;
        #pragma unroll
        for (int c4 = 0; c4 < 16; c4++) {
            float4 xv = *(const float4*)(xr + c4 * 4);
            float4 w0 = *(const float4*)(wr + 0 * 68 + c4 * 4);
            float4 w1 = *(const float4*)(wr + 1 * 68 + c4 * 4);
            float4 w2 = *(const float4*)(wr + 2 * 68 + c4 * 4);
            float4 w3 = *(const float4*)(wr + 3 * 68 + c4 * 4);
            acc.x = fmaf(xv.x, w0.x, fmaf(xv.y, w0.y, fmaf(xv.z, w0.z, fmaf(xv.w, w0.w, acc.x))));
            acc.y = fmaf(xv.x, w1.x, fmaf(xv.y, w1.y, fmaf(xv.z, w1.z, fmaf(xv.w, w1.w, acc.y))));
            acc.z = fmaf(xv.x, w2.x, fmaf(xv.y, w2.y, fmaf(xv.z, w2.z, fmaf(xv.w, w2.w, acc.z))));
            acc.w = fmaf(xv.x, w3.x, fmaf(xv.y, w3.y, fmaf(xv.z, w3.z, fmaf(xv.w, w3.w, acc.w))));
        }
        float4 bv = *(const float4*)(b1 + oh * 4);
        acc.x += bv.x; acc.y += bv.y; acc.z += bv.z; acc.w += bv.w;
        *(float4*)(V1s + ii * 64 + oh * 4) = acc;
        __syncthreads();
    }

    // ------------------- Phase A3: W4, biases, tiled transposes -------------------
    {
        // per-pair quadratic weights (W4s region free after A2's sync)
        const int i = tid >> 4, jj = tid & 15;
        float d = dist[(m * 64 + i) * 64 + j0 + jj];
        float t = d * INV_H;
        int k = __float2int_rn(t);
        k = min(max(k, 1), S_INT - 1);
        float u = t - (float)k;
        float wm = 0.5f * u * (u - 1.0f);
        float w0 = 1.0f - u * u;
        float wp = 0.5f * u * (u + 1.0f);
        float4 wk;
        wk.x = __uint_as_float(h2bits(wm));
        wk.y = __uint_as_float(h2bits(w0));
        wk.z = __uint_as_float(h2bits(wp));
        wk.w = __int_as_float((k - 1) << 7);   // byte offset of first tap row
        ((float4*)W4s)[tid] = wk;

        if (tid < 64) B2s[tid] = b2[tid];
        else if (tid < 128) B3s[tid - 64] = b3[tid - 64];
    }
    // W2^T via padded tile: coalesced LDG, conflict-free STS/LDS
    {
        #pragma unroll 4
        for (int k = 0; k < 4; k++) {
            int idx = tid + (k << 10);
            Ttile[(idx >> 6) * 65 + (idx & 63)] = __ldg(&W2[idx]);
        }
        __syncthreads();
        #pragma unroll 4
        for (int k = 0; k < 4; k++) {
            int idx = tid + (k << 10);
            int r = idx >> 6, c = idx & 63;
            W2Ts[idx] = Ttile[c * 65 + r];   // W2^T[r][c] = W2[c][r]
        }
        __syncthreads();
        #pragma unroll 4
        for (int k = 0; k < 4; k++) {
            int idx = tid + (k << 10);
            Ttile[(idx >> 6) * 65 + (idx & 63)] = __ldg(&W3[idx]);
        }
        __syncthreads();
        #pragma unroll 4
        for (int k = 0; k < 4; k++) {
            int idx = tid + (k << 10);
            int r = idx >> 6, c = idx & 63;
            W3Ts[idx] = Ttile[c * 65 + r];
        }
    }

    // ------------------- Grid barrier (table visibility) -------------------
    __threadfence();
    __syncthreads();
    if (tid == 0) {
        unsigned old = atomicAdd(&g_bar, 1u);
        unsigned target = (old & ~127u) + 128u;
        while (*((volatile unsigned*)&g_bar) < target) { __nanosleep(64); }
        __threadfence();
    }
    __syncthreads();

    // ------------------- Phase B: depth-2 pipelined main loop -------------------
    const int warp  = tid >> 5;
    const int jj    = warp & 15;     // destination atom
    const int ihalf = warp >> 4;     // 0..1 : i-range half
    const int t     = tid & 31;
    const int half  = t >> 4;        // even/odd i within the half-warp
    const int q     = t & 15;        // channel quad: channels 4q..4q+3

    u64 acc0 = 0ull, acc1 = 0ull;
    const char* tbg = (const char*)g_table_h + (q << 3);    // GLOBAL, L1-cached
    const char* v1b = (const char*)V1s + (q << 4);
    const float4* W4v = ((const float4*)W4s) + jj;
    const int i0 = (ihalf << 5) + half;                     // start i, step 2

    // prologue: load iteration 0 fully
    float4 wk = W4v[i0 << 4];
    int koff = __float_as_int(wk.w);
    uint2 r0 = __ldg((const uint2*)(tbg + koff));
    uint2 r1 = __ldg((const uint2*)(tbg + koff + 128));
    uint2 r2 = __ldg((const uint2*)(tbg + koff + 256));
    ulonglong2 vv = *(const ulonglong2*)(v1b + (i0 << 8));

    #pragma unroll 4
    for (int ii = 0; ii < 16; ii++) {
        // prefetch iteration ii+1 (loads overlap current compute)
        float4 wk_n = wk; uint2 s0 = r0, s1 = r1, s2 = r2; ulonglong2 vv_n = vv;
        if (ii < 15) {
            const int inext = i0 + ((ii + 1) << 1);
            wk_n = W4v[inext << 4];
            int koff_n = __float_as_int(wk_n.w);
            s0 = __ldg((const uint2*)(tbg + koff_n));
            s1 = __ldg((const uint2*)(tbg + koff_n + 128));
            s2 = __ldg((const uint2*)(tbg + koff_n + 256));
            vv_n = *(const ulonglong2*)(v1b + (inext << 8));
        }
        // compute current
        __half2 wm2 = bits2h(__float_as_uint(wk.x));
        __half2 w02 = bits2h(__float_as_uint(wk.y));
        __half2 wp2 = bits2h(__float_as_uint(wk.z));
        __half2 hA = __hfma2(wm2, bits2h(r0.x),
                     __hfma2(w02, bits2h(r1.x), __hmul2(wp2, bits2h(r2.x))));
        __half2 hB = __hfma2(wm2, bits2h(r0.y),
                     __hfma2(w02, bits2h(r1.y), __hmul2(wp2, bits2h(r2.y))));
        float2 fA = __half22float2(hA);
        float2 fB = __half22float2(hB);
        acc0 = fma2(vv.x, pack2(fA.x, fA.y), acc0);
        acc1 = fma2(vv.y, pack2(fB.x, fB.y), acc1);
        wk = wk_n; r0 = s0; r1 = s1; r2 = s2; vv = vv_n;
    }
    {
        const int slice = (ihalf << 1) | half;              // 0..3
        ulonglong2 r; r.x = acc0; r.y = acc1;
        ((ulonglong2*)PARTs)[slice * 256 + (jj << 4) + q] = r;
    }
    __syncthreads();

    // reduce 4 slices
    if (tid < 256) {
        const ulonglong2* pp = (const ulonglong2*)PARTs;
        ulonglong2 a0 = pp[tid];
        ulonglong2 a1 = pp[256 + tid];
        ulonglong2 a2 = pp[512 + tid];
        ulonglong2 a3 = pp[768 + tid];
        ulonglong2 r;
        r.x = add2(add2(a0.x, a1.x), add2(a2.x, a3.x));
        r.y = add2(add2(a0.y, a1.y), add2(a2.y, a3.y));
        ((ulonglong2*)PAIRs)[tid] = r;
    }
    __syncthreads();

    // epilogue: 8 warps, each handles 2 j-rows; lane = output pair (2t,2t+1)
    if (tid < 256) {
        const int g  = tid >> 5;      // 0..7
        const int tt = tid & 31;
        const int jj0 = g, jj1 = g + 8;

        u64 a0, a1;
        {
            u64 bp = ((const u64*)B2s)[tt];
            a0 = bp; a1 = bp;
            const float4* pr0 = (const float4*)(PAIRs + jj0 * 64);
            const float4* pr1 = (const float4*)(PAIRs + jj1 * 64);
            const u64* wv = (const u64*)W2Ts;
            #pragma unroll 4
            for (int c4 = 0; c4 < 16; c4++) {
                float4 p0 = pr0[c4];
                float4 p1 = pr1[c4];
                u64 w0 = wv[(c4 * 4 + 0) * 32 + tt];
                u64 w1 = wv[(c4 * 4 + 1) * 32 + tt];
                u64 w2 = wv[(c4 * 4 + 2) * 32 + tt];
                u64 w3 = wv[(c4 * 4 + 3) * 32 + tt];
                a0 = fma2(dup2(p0.x), w0, a0); a1 = fma2(dup2(p1.x), w0, a1);
                a0 = fma2(dup2(p0.y), w1, a0); a1 = fma2(dup2(p1.y), w1, a1);
                a0 = fma2(dup2(p0.z), w2, a0); a1 = fma2(dup2(p1.z), w2, a1);
                a0 = fma2(dup2(p0.w), w3, a0); a1 = fma2(dup2(p1.w), w3, a1);
            }
            float2 f0 = unpk2(a0), f1 = unpk2(a1);
            ((u64*)V2s)[jj0 * 32 + tt] = pack2(softplus_f(f0.x), softplus_f(f0.y));
            ((u64*)V2s)[jj1 * 32 + tt] = pack2(softplus_f(f1.x), softplus_f(f1.y));
        }
        __syncwarp();

        {
            u64 bp = ((const u64*)B3s)[tt];
            a0 = bp; a1 = bp;
            const float4* pr0 = (const float4*)(V2s + jj0 * 64);
            const float4* pr1 = (const float4*)(V2s + jj1 * 64);
            const u64* wv = (const u64*)W3Ts;
            #pragma unroll 4
            for (int c4 = 0; c4 < 16; c4++) {
                float4 p0 = pr0[c4];
                float4 p1 = pr1[c4];
                u64 w0 = wv[(c4 * 4 + 0) * 32 + tt];
                u64 w1 = wv[(c4 * 4 + 1) * 32 + tt];
                u64 w2 = wv[(c4 * 4 + 2) * 32 + tt];
                u64 w3 = wv[(c4 * 4 + 3) * 32 + tt];
                a0 = fma2(dup2(p0.x), w0, a0); a1 = fma2(dup2(p1.x), w0, a1);
                a0 = fma2(dup2(p0.y), w1, a0); a1 = fma2(dup2(p1.y), w1, a1);
                a0 = fma2(dup2(p0.z), w2, a0); a1 = fma2(dup2(p1.z), w2, a1);
                a0 = fma2(dup2(p0.w), w3, a0); a1 = fma2(dup2(p1.w), w3, a1);
            }
            const u64* xv = (const u64*)x;
            u64* ov = (u64*)out;
            int g0 = (m * 64 + j0 + jj0) * 32 + tt;
            int g1 = (m * 64 + j0 + jj1) * 32 + tt;
            float2 f0 = unpk2(a0), x0 = unpk2(xv[g0]);
            float2 f1 = unpk2(a1), x1 = unpk2(xv[g1]);
            ov[g0] = pack2(f0.x + x0.x, f0.y + x0.y);
            ov[g1] = pack2(f1.x + x1.x, f1.y + x1.y);
        }
    }
}

extern "C" void kernel_launch(void* const* d_in, const int* in_sizes, int n_in,
                              void* d_out, int out_size) {
    const float* x   = (const float*)d_in[0];
    const float* dist= (const float*)d_in[1];
    const float* W1  = (const float*)d_in[2];
    const float* b1  = (const float*)d_in[3];
    const float* W2  = (const float*)d_in[4];
    const float* b2  = (const float*)d_in[5];
    const float* W3  = (const float*)d_in[6];
    const float* b3  = (const float*)d_in[7];
    const float* Wd1 = (const float*)d_in[8];
    const float* bd1 = (const float*)d_in[9];
    const float* Wd2 = (const float*)d_in[10];
    const float* bd2 = (const float*)d_in[11];
    float* out = (float*)d_out;
    (void)in_sizes; (void)n_in; (void)out_size;

    cudaFuncSetAttribute(fused_kernel, cudaFuncAttributeMaxDynamicSharedMemorySize, MAIN_SMEM);
    fused_kernel<<<128, 1024, MAIN_SMEM>>>(x, dist, W1, b1, W2, b2, W3, b3,
                                           Wd1, bd1, Wd2, bd2, out);
}